// round 7
// baseline (speedup 1.0000x reference)
#include <cuda_runtime.h>
#include <math.h>

#define NN 256
#define BATCH 4096
#define TROWS 520          // padded step rows (active t: 0..508; rows 509+ identity)

typedef unsigned long long u64;

// Packed coefficient records: per (t,m) two ulonglong2:
//   q0 = { c2=[c,c],   sr2=[sr,sr] }
//   q1 = { si2=[si,si], nsr2=[-sr,-sr] }
__device__ ulonglong2 g_cp[TROWS * 128 * 2];   // 2.13 MB
__device__ float g_Wt[NN * NN];                // g_Wt[j*NN + i] = Re(e^{i phe_i} U[i][j])

// ---------------------------------------------------------------------------
// f32x2 helpers (Blackwell packed fp32; PTX-only, no C++ lowering)
// ---------------------------------------------------------------------------
__device__ __forceinline__ u64 mul2(u64 a, u64 b) {
    u64 d; asm("mul.rn.f32x2 %0,%1,%2;" : "=l"(d) : "l"(a), "l"(b)); return d;
}
__device__ __forceinline__ u64 fma2(u64 a, u64 b, u64 c) {
    u64 d; asm("fma.rn.f32x2 %0,%1,%2,%3;" : "=l"(d) : "l"(a), "l"(b), "l"(c)); return d;
}
// w = [-y, x] from v = [x, y]  (1 xor + pack; alu pipe)
__device__ __forceinline__ u64 wrot(u64 v) {
    unsigned x, y;
    asm("mov.b64 {%0,%1},%2;" : "=r"(x), "=r"(y) : "l"(v));
    unsigned ny = y ^ 0x80000000u;
    u64 w; asm("mov.b64 %0,{%1,%2};" : "=l"(w) : "r"(ny), "r"(x)); return w;
}
__device__ __forceinline__ u64 dup2(unsigned s) {
    u64 d; asm("mov.b64 %0,{%1,%1};" : "=l"(d) : "r"(s)); return d;
}
__device__ __forceinline__ unsigned lo32(u64 v) {
    unsigned x, y;
    asm("mov.b64 {%0,%1},%2;" : "=r"(x), "=r"(y) : "l"(v)); return x;
}

// ---------------------------------------------------------------------------
// Kernel A: schedule-ordered packed coefficients (identity for inactive slots)
// ---------------------------------------------------------------------------
__global__ void coefp_kernel(const float* __restrict__ theta,
                             const float* __restrict__ phi) {
    const int t = blockIdx.x;        // 0..TROWS-1
    const int m = threadIdx.x;       // 0..127
    const int p = 2 * m + (t & 1);
    const int pmaxs = min(t, 508 - t);
    float c = 1.f, sr = 0.f, si = 0.f;
    if (p <= pmaxs) {
        const int l = (t - p) >> 1;
        const int idx = l * 255 - ((l * (l - 1)) >> 1) + p;
        float s, cc;  sincosf(theta[idx], &s, &cc);
        float ei, er; sincosf(phi[idx], &ei, &er);
        c = cc; sr = s * er; si = s * ei;
    }
    const unsigned uc = __float_as_uint(c);
    const unsigned us = __float_as_uint(sr);
    const unsigned ui = __float_as_uint(si);
    const unsigned un = us ^ 0x80000000u;
    const u64 c2  = ((u64)uc << 32) | uc;
    const u64 sr2 = ((u64)us << 32) | us;
    const u64 si2 = ((u64)ui << 32) | ui;
    const u64 ns2 = ((u64)un << 32) | un;
    const int base = (t * 128 + m) * 2;
    g_cp[base]     = make_ulonglong2(c2, sr2);
    g_cp[base + 1] = make_ulonglong2(si2, ns2);
}

// ---------------------------------------------------------------------------
// Kernel B: warp-per-column systolic build, packed-complex state.
// Lane i holds rows 8i..8i+7 as u64 V[k]=[x,y]. 6 f32x2 ops per MZI
// (vs 12 scalar FFMA) -> fma-pipe floor halves. Identity-padded schedule
// keeps the loop branch-free; 4-row register ring prefetches coefs.
// ---------------------------------------------------------------------------
#define MZI2(C2, SR2, SI2, NS2, Va, Vb) do {          \
    const u64 w1_ = wrot(Vb), w0_ = wrot(Va);         \
    u64 t0_ = mul2((C2), (Va));                       \
    t0_ = fma2((NS2), (Vb), t0_);                     \
    t0_ = fma2((SI2), w1_, t0_);                      \
    u64 t1_ = mul2((SR2), (Va));                      \
    t1_ = fma2((SI2), w0_, t1_);                      \
    (Vb) = fma2((C2), (Vb), t1_);                     \
    (Va) = t0_;                                       \
} while (0)

#define LOADROW(s, tt) do {                                        \
    const ulonglong2* q_ = &g_cp[((tt) * 128 + 4 * lane) * 2];     \
    _Pragma("unroll")                                              \
    for (int k_ = 0; k_ < 4; ++k_) {                               \
        const ulonglong2 a_ = __ldg(q_ + 2 * k_);                  \
        const ulonglong2 b_ = __ldg(q_ + 2 * k_ + 1);              \
        rc[s][k_] = a_.x; rs[s][k_] = a_.y;                        \
        ri[s][k_] = b_.x; rn[s][k_] = b_.y;                        \
    }                                                              \
} while (0)

#define STEP_EVEN(s) do {                                          \
    MZI2(rc[s][0], rs[s][0], ri[s][0], rn[s][0], V[0], V[1]);      \
    MZI2(rc[s][1], rs[s][1], ri[s][1], rn[s][1], V[2], V[3]);      \
    MZI2(rc[s][2], rs[s][2], ri[s][2], rn[s][2], V[4], V[5]);      \
    MZI2(rc[s][3], rs[s][3], ri[s][3], rn[s][3], V[6], V[7]);      \
} while (0)

#define STEP_ODD(s) do {                                           \
    const u64 dn_ = __shfl_down_sync(0xffffffffu, V[0], 1);        \
    const u64 up_ = __shfl_up_sync(0xffffffffu, V[7], 1);          \
    unsigned cl_ = __shfl_up_sync(0xffffffffu, lo32(rc[s][3]), 1); \
    unsigned sl_ = __shfl_up_sync(0xffffffffu, lo32(rs[s][3]), 1); \
    unsigned il_ = __shfl_up_sync(0xffffffffu, lo32(ri[s][3]), 1); \
    if (lane == 0) { cl_ = 0x3f800000u; sl_ = 0u; il_ = 0u; }      \
    const u64 C2p = dup2(cl_), SR2p = dup2(sl_), SI2p = dup2(il_); \
    MZI2(rc[s][0], rs[s][0], ri[s][0], rn[s][0], V[1], V[2]);      \
    MZI2(rc[s][1], rs[s][1], ri[s][1], rn[s][1], V[3], V[4]);      \
    MZI2(rc[s][2], rs[s][2], ri[s][2], rn[s][2], V[5], V[6]);      \
    {   /* upper boundary: my row7 = v0, next lane row0 = v1 */    \
        const u64 w1_ = wrot(dn_);                                 \
        u64 t0_ = mul2(rc[s][3], V[7]);                            \
        t0_ = fma2(rn[s][3], dn_, t0_);                            \
        V[7] = fma2(ri[s][3], w1_, t0_);                           \
    }                                                              \
    {   /* lower boundary: prev lane row7 = v0, my row0 = v1 */    \
        const u64 w0_ = wrot(up_);                                 \
        u64 t1_ = mul2(SR2p, up_);                                 \
        t1_ = fma2(SI2p, w0_, t1_);                                \
        V[0] = fma2(C2p, V[0], t1_);                               \
    }                                                              \
} while (0)

__global__ __launch_bounds__(128, 1) void build_u_kernel(const float* __restrict__ phi_ext) {
    const int lane = threadIdx.x & 31;
    const int j = blockIdx.x * 4 + (threadIdx.x >> 5);   // column, one per warp

    u64 V[8];
    #pragma unroll
    for (int k = 0; k < 8; ++k)
        V[k] = (u64)__float_as_uint((8 * lane + k == j) ? 1.f : 0.f);  // [x, 0]

    u64 rc[4][4], rs[4][4], ri[4][4], rn[4][4];
    LOADROW(0, 0); LOADROW(1, 1); LOADROW(2, 2); LOADROW(3, 3);

    int t = 4;
    #pragma unroll 1
    for (int it = 0; it < 128; ++it) {   // 128*4 = 512 steps (509 active + 3 identity)
        STEP_EVEN(0); LOADROW(0, t);
        STEP_ODD(1);  LOADROW(1, t + 1);
        STEP_EVEN(2); LOADROW(2, t + 2);
        STEP_ODD(3);  LOADROW(3, t + 3);
        t += 4;
    }

    // phase screen, real part, store column j (transposed W)
    #pragma unroll
    for (int k = 0; k < 8; ++k) {
        const int r = 8 * lane + k;
        float sp, cp;
        sincosf(__ldg(&phi_ext[r]), &sp, &cp);
        const float x = __uint_as_float((unsigned)(V[k] & 0xffffffffull));
        const float y = __uint_as_float((unsigned)(V[k] >> 32));
        g_Wt[j * NN + r] = cp * x - sp * y;
    }
}

// ---------------------------------------------------------------------------
// Kernel C: out[b,i] = sum_j x[b,j] * Wt[j,i]
// BM=BN=64, BK=16, 256 threads, 4x4 per thread, float4 smem paths (pad +4).
// ---------------------------------------------------------------------------
#define BM 64
#define BN 64
#define BK 16

__global__ __launch_bounds__(256, 4) void gemm_kernel(const float* __restrict__ A,
                                                      float* __restrict__ C) {
    __shared__ float As[BK][BM + 4];
    __shared__ float Ws[BK][BN + 4];

    const int tid = threadIdx.x;
    const int tx = tid & 15;
    const int ty = tid >> 4;
    const int bm0 = blockIdx.x * BM;
    const int bn0 = blockIdx.y * BN;

    const int lr = tid >> 2;
    const int lc = (tid & 3) * 4;
    const int wr = tid >> 4;
    const int wc = (tid & 15) * 4;

    float acc[4][4] = {};

    for (int k0 = 0; k0 < NN; k0 += BK) {
        const float4 a4 = *reinterpret_cast<const float4*>(A + (bm0 + lr) * NN + k0 + lc);
        As[lc + 0][lr] = a4.x; As[lc + 1][lr] = a4.y;
        As[lc + 2][lr] = a4.z; As[lc + 3][lr] = a4.w;
        const float4 w4 = *reinterpret_cast<const float4*>(g_Wt + (k0 + wr) * NN + bn0 + wc);
        *reinterpret_cast<float4*>(&Ws[wr][wc]) = w4;
        __syncthreads();

        #pragma unroll
        for (int k = 0; k < BK; ++k) {
            const float4 am = *reinterpret_cast<const float4*>(&As[k][ty * 4]);
            const float4 bn = *reinterpret_cast<const float4*>(&Ws[k][tx * 4]);
            const float a[4] = {am.x, am.y, am.z, am.w};
            const float b[4] = {bn.x, bn.y, bn.z, bn.w};
            #pragma unroll
            for (int i = 0; i < 4; ++i)
                #pragma unroll
                for (int jj = 0; jj < 4; ++jj)
                    acc[i][jj] = fmaf(a[i], b[jj], acc[i][jj]);
        }
        __syncthreads();
    }

    #pragma unroll
    for (int i = 0; i < 4; ++i) {
        float4 r = make_float4(acc[i][0], acc[i][1], acc[i][2], acc[i][3]);
        *reinterpret_cast<float4*>(C + (bm0 + ty * 4 + i) * NN + bn0 + tx * 4) = r;
    }
}

// ---------------------------------------------------------------------------
// Launch: inputs (metadata order): x, theta, phi_internal, phi_external
// ---------------------------------------------------------------------------
extern "C" void kernel_launch(void* const* d_in, const int* in_sizes, int n_in,
                              void* d_out, int out_size) {
    const float* x       = (const float*)d_in[0];
    const float* theta   = (const float*)d_in[1];
    const float* phi_int = (const float*)d_in[2];
    const float* phi_ext = (const float*)d_in[3];
    float* out = (float*)d_out;

    coefp_kernel<<<TROWS, 128>>>(theta, phi_int);
    build_u_kernel<<<NN / 4, 128>>>(phi_ext);
    gemm_kernel<<<dim3(BATCH / BM, NN / BN), 256>>>(x, out);
}

// round 8
// speedup vs baseline: 1.7725x; 1.7725x over previous
#include <cuda_runtime.h>
#include <math.h>

#define NN 256
#define BATCH 4096
#define TROWS 520          // padded step rows (active t: 0..508)

// Scratch (no device allocations allowed)
__device__ float4 g_coef2[TROWS * 128];  // [t][m]: coef for MZI at p=2m+(t&1); identity if inactive
__device__ float  g_Wt[NN * NN];         // g_Wt[j*NN + i] = Re(e^{i phe_i} U[i][j])

// ---------------------------------------------------------------------------
// Kernel A: schedule-ordered coefficients. (t,m) <-> (layer l, pos p) bijection
// on active entries; inactive slots get identity (1,0,0) so the build kernel
// needs no predication at all.
// ---------------------------------------------------------------------------
__global__ void coef2_kernel(const float* __restrict__ theta,
                             const float* __restrict__ phi) {
    const int t = blockIdx.x;        // 0..TROWS-1
    const int m = threadIdx.x;       // 0..127
    const int p = 2 * m + (t & 1);
    const int pmaxs = min(t, 508 - t);   // negative for t > 508
    float4 out = make_float4(1.f, 0.f, 0.f, 0.f);
    if (p <= pmaxs) {                // implies t <= 508, p <= 254, l in range
        const int l = (t - p) >> 1;
        const int idx = l * 255 - ((l * (l - 1)) >> 1) + p;
        float s, c;  sincosf(theta[idx], &s, &c);
        float ei, er; sincosf(phi[idx], &ei, &er);
        out = make_float4(c, s * er, s * ei, 0.f);
    }
    g_coef2[t * 128 + m] = out;
}

// ---------------------------------------------------------------------------
// Kernel B: one warp per column; rows 8i..8i+7 in lane i's registers.
// Even step: 4 internal MZIs (rows 0-1,2-3,4-5,6-7). Odd step: 3 internal
// (1-2,3-4,5-6) + boundary (7 | next lane's 0) via shfl. Identity coefs make
// the loop branch-free. 3-pair coef prefetch pipeline (~4-step lead).
// 256 threads / 8 warps per CTA -> 2 warps per SMSP so independent columns
// hide each other's shfl/FMA latency; FMA-pipe issue becomes the limit.
// ---------------------------------------------------------------------------
#define MZI(cf, x0, y0, x1, y1) do {                       \
    const float c_ = (cf).x, sr_ = (cf).y, si_ = (cf).z;   \
    const float nx0 = c_*(x0) - sr_*(x1) - si_*(y1);       \
    const float ny0 = c_*(y0) - sr_*(y1) + si_*(x1);       \
    const float nx1 = sr_*(x0) - si_*(y0) + c_*(x1);       \
    const float ny1 = sr_*(y0) + si_*(x0) + c_*(y1);       \
    (x0) = nx0; (y0) = ny0; (x1) = nx1; (y1) = ny1;        \
} while (0)

#define LOADP(dst, tt) do {                                            \
    const float4* p_ = &g_coef2[(tt) * 128 + 4 * lane];                \
    dst[0] = __ldg(p_ + 0); dst[1] = __ldg(p_ + 1);                    \
    dst[2] = __ldg(p_ + 2); dst[3] = __ldg(p_ + 3);                    \
} while (0)

#define STEP_EVEN(cf) do {                                             \
    MZI(cf[0], vr[0], vi[0], vr[1], vi[1]);                            \
    MZI(cf[1], vr[2], vi[2], vr[3], vi[3]);                            \
    MZI(cf[2], vr[4], vi[4], vr[5], vi[5]);                            \
    MZI(cf[3], vr[6], vi[6], vr[7], vi[7]);                            \
} while (0)

#define STEP_ODD(cf) do {                                              \
    /* shfls first: vr/vi[0] and [7] untouched by interior MZIs */     \
    const float rx = __shfl_down_sync(0xffffffffu, vr[0], 1);          \
    const float ry = __shfl_down_sync(0xffffffffu, vi[0], 1);          \
    const float lx = __shfl_up_sync(0xffffffffu, vr[7], 1);            \
    const float ly = __shfl_up_sync(0xffffffffu, vi[7], 1);            \
    float bc = __shfl_up_sync(0xffffffffu, cf[3].x, 1);                \
    float bs = __shfl_up_sync(0xffffffffu, cf[3].y, 1);                \
    float bt = __shfl_up_sync(0xffffffffu, cf[3].z, 1);                \
    if (lane == 0) { bc = 1.f; bs = 0.f; bt = 0.f; }                   \
    MZI(cf[0], vr[1], vi[1], vr[2], vi[2]);                            \
    MZI(cf[1], vr[3], vi[3], vr[4], vi[4]);                            \
    MZI(cf[2], vr[5], vi[5], vr[6], vi[6]);                            \
    {   /* upper boundary: this lane's row 7 is v0 -> n0 */            \
        const float c_ = cf[3].x, sr_ = cf[3].y, si_ = cf[3].z;        \
        const float nx = c_*vr[7] - sr_*rx - si_*ry;                   \
        const float ny = c_*vi[7] - sr_*ry + si_*rx;                   \
        vr[7] = nx; vi[7] = ny;                                        \
    }                                                                  \
    {   /* lower boundary: this lane's row 0 is v1 -> n1 */            \
        const float nx = bs*lx - bt*ly + bc*vr[0];                     \
        const float ny = bs*ly + bt*lx + bc*vi[0];                     \
        vr[0] = nx; vi[0] = ny;                                        \
    }                                                                  \
} while (0)

__global__ __launch_bounds__(256, 1) void build_u_kernel(const float* __restrict__ phi_ext) {
    const int lane = threadIdx.x & 31;
    const int j = blockIdx.x * 8 + (threadIdx.x >> 5);   // column, one per warp

    float vr[8], vi[8];
    #pragma unroll
    for (int k = 0; k < 8; ++k) {
        vr[k] = (8 * lane + k == j) ? 1.f : 0.f;
        vi[k] = 0.f;
    }

    float4 e0[4], o0[4], e1[4], o1[4], e2[4], o2[4];
    LOADP(e0, 0); LOADP(o0, 1);
    LOADP(e1, 2); LOADP(o1, 3);
    LOADP(e2, 4); LOADP(o2, 5);

    int t = 6;
    #pragma unroll 1
    for (int it = 0; it < 85; ++it) {     // 85*6 = 510 steps (0..509; 509 inert)
        STEP_EVEN(e0); STEP_ODD(o0); LOADP(e0, t);     LOADP(o0, t + 1);
        STEP_EVEN(e1); STEP_ODD(o1); LOADP(e1, t + 2); LOADP(o1, t + 3);
        STEP_EVEN(e2); STEP_ODD(o2); LOADP(e2, t + 4); LOADP(o2, t + 5);
        t += 6;
    }

    // phase screen, real part, store column j (transposed W)
    #pragma unroll
    for (int k = 0; k < 8; ++k) {
        const int r = 8 * lane + k;
        float sp, cp;
        sincosf(__ldg(&phi_ext[r]), &sp, &cp);
        g_Wt[j * NN + r] = cp * vr[k] - sp * vi[k];
    }
}

// ---------------------------------------------------------------------------
// Kernel C: out[b,i] = sum_j x[b,j] * Wt[j,i]
// BM=BN=64, BK=16, 256 threads, 4x4 per thread, float4 smem paths (pad +4).
// ---------------------------------------------------------------------------
#define BM 64
#define BN 64
#define BK 16

__global__ __launch_bounds__(256, 4) void gemm_kernel(const float* __restrict__ A,
                                                      float* __restrict__ C) {
    __shared__ float As[BK][BM + 4];
    __shared__ float Ws[BK][BN + 4];

    const int tid = threadIdx.x;
    const int tx = tid & 15;
    const int ty = tid >> 4;
    const int bm0 = blockIdx.x * BM;
    const int bn0 = blockIdx.y * BN;

    const int lr = tid >> 2;
    const int lc = (tid & 3) * 4;
    const int wr = tid >> 4;
    const int wc = (tid & 15) * 4;

    float acc[4][4] = {};

    for (int k0 = 0; k0 < NN; k0 += BK) {
        const float4 a4 = *reinterpret_cast<const float4*>(A + (bm0 + lr) * NN + k0 + lc);
        As[lc + 0][lr] = a4.x; As[lc + 1][lr] = a4.y;
        As[lc + 2][lr] = a4.z; As[lc + 3][lr] = a4.w;
        const float4 w4 = *reinterpret_cast<const float4*>(g_Wt + (k0 + wr) * NN + bn0 + wc);
        *reinterpret_cast<float4*>(&Ws[wr][wc]) = w4;
        __syncthreads();

        #pragma unroll
        for (int k = 0; k < BK; ++k) {
            const float4 am = *reinterpret_cast<const float4*>(&As[k][ty * 4]);
            const float4 bn = *reinterpret_cast<const float4*>(&Ws[k][tx * 4]);
            const float a[4] = {am.x, am.y, am.z, am.w};
            const float b[4] = {bn.x, bn.y, bn.z, bn.w};
            #pragma unroll
            for (int i = 0; i < 4; ++i)
                #pragma unroll
                for (int jj = 0; jj < 4; ++jj)
                    acc[i][jj] = fmaf(a[i], b[jj], acc[i][jj]);
        }
        __syncthreads();
    }

    #pragma unroll
    for (int i = 0; i < 4; ++i) {
        float4 r = make_float4(acc[i][0], acc[i][1], acc[i][2], acc[i][3]);
        *reinterpret_cast<float4*>(C + (bm0 + ty * 4 + i) * NN + bn0 + tx * 4) = r;
    }
}

// ---------------------------------------------------------------------------
// Launch: inputs (metadata order): x, theta, phi_internal, phi_external
// ---------------------------------------------------------------------------
extern "C" void kernel_launch(void* const* d_in, const int* in_sizes, int n_in,
                              void* d_out, int out_size) {
    const float* x       = (const float*)d_in[0];
    const float* theta   = (const float*)d_in[1];
    const float* phi_int = (const float*)d_in[2];
    const float* phi_ext = (const float*)d_in[3];
    float* out = (float*)d_out;

    coef2_kernel<<<TROWS, 128>>>(theta, phi_int);
    build_u_kernel<<<NN / 8, 256>>>(phi_ext);
    gemm_kernel<<<dim3(BATCH / BM, NN / BN), 256>>>(x, out);
}

// round 9
// speedup vs baseline: 3.8045x; 2.1463x over previous
#include <cuda_runtime.h>
#include <math.h>

#define NN 256
#define BATCH 4096
#define TROWS 520          // padded step rows (active t: 0..508)

// Scratch (no device allocations allowed)
// SoA layout: g_coef2[t*128 + k*32 + lane] = coef for slot m = 4*lane + k
// (MZI at p = 2m + (t&1)); identity if inactive. Lane stride 16B -> nL=4.
__device__ float4 g_coef2[TROWS * 128];
// Boundary coef for odd steps: g_coefB[t*32 + lane] = coef of slot 4*lane - 1
// (identity for lane 0). Avoids 3 shfls per odd step.
__device__ float4 g_coefB[TROWS * 32];
__device__ float  g_Wt[NN * NN];         // g_Wt[j*NN + i] = Re(e^{i phe_i} U[i][j])

// ---------------------------------------------------------------------------
// Kernel A: schedule-ordered coefficients, SoA + boundary plane.
// ---------------------------------------------------------------------------
__global__ void coef2_kernel(const float* __restrict__ theta,
                             const float* __restrict__ phi) {
    const int t = blockIdx.x;        // 0..TROWS-1
    const int m = threadIdx.x;       // 0..127 (slot)
    const int p = 2 * m + (t & 1);
    const int pmaxs = min(t, 508 - t);   // negative for t > 508
    float4 out = make_float4(1.f, 0.f, 0.f, 0.f);
    if (p <= pmaxs) {                // implies t <= 508, p <= 254, l in range
        const int l = (t - p) >> 1;
        const int idx = l * 255 - ((l * (l - 1)) >> 1) + p;
        float s, c;  sincosf(theta[idx], &s, &c);
        float ei, er; sincosf(phi[idx], &ei, &er);
        out = make_float4(c, s * er, s * ei, 0.f);
    }
    g_coef2[t * 128 + (m & 3) * 32 + (m >> 2)] = out;
    // boundary plane: slot m = 4i-1 feeds lane i's lower boundary
    if ((m & 3) == 3 && m < 127)
        g_coefB[t * 32 + ((m + 1) >> 2)] = out;
    if (m == 0)
        g_coefB[t * 32] = make_float4(1.f, 0.f, 0.f, 0.f);
}

// ---------------------------------------------------------------------------
// Kernel B: one warp per column; rows 8i..8i+7 in lane i's registers.
// Even step: 4 internal MZIs. Odd step: 3 internal + two boundary halves
// (values via 4 shfls; boundary coef preloaded from g_coefB). Identity
// padding keeps the loop branch-free. 6-row register prefetch ring.
// 128 thr/CTA, 64 CTAs -> 1 warp/SMSP (measured optimum).
// ---------------------------------------------------------------------------
#define MZI(cf, x0, y0, x1, y1) do {                       \
    const float c_ = (cf).x, sr_ = (cf).y, si_ = (cf).z;   \
    const float nx0 = c_*(x0) - sr_*(x1) - si_*(y1);       \
    const float ny0 = c_*(y0) - sr_*(y1) + si_*(x1);       \
    const float nx1 = sr_*(x0) - si_*(y0) + c_*(x1);       \
    const float ny1 = sr_*(y0) + si_*(x0) + c_*(y1);       \
    (x0) = nx0; (y0) = ny0; (x1) = nx1; (y1) = ny1;        \
} while (0)

#define LOADP(dst, tt) do {                                            \
    const float4* p_ = &g_coef2[(tt) * 128 + lane];                    \
    dst[0] = __ldg(p_);       dst[1] = __ldg(p_ + 32);                 \
    dst[2] = __ldg(p_ + 64);  dst[3] = __ldg(p_ + 96);                 \
} while (0)

#define LOADB(bdst, tt) do {                                           \
    bdst = __ldg(&g_coefB[(tt) * 32 + lane]);                          \
} while (0)

#define STEP_EVEN(cf) do {                                             \
    MZI(cf[0], vr[0], vi[0], vr[1], vi[1]);                            \
    MZI(cf[1], vr[2], vi[2], vr[3], vi[3]);                            \
    MZI(cf[2], vr[4], vi[4], vr[5], vi[5]);                            \
    MZI(cf[3], vr[6], vi[6], vr[7], vi[7]);                            \
} while (0)

#define STEP_ODD(cf, bcf) do {                                         \
    /* shfls first: vr/vi[0] and [7] untouched by interior MZIs */     \
    const float rx = __shfl_down_sync(0xffffffffu, vr[0], 1);          \
    const float ry = __shfl_down_sync(0xffffffffu, vi[0], 1);          \
    const float lx = __shfl_up_sync(0xffffffffu, vr[7], 1);            \
    const float ly = __shfl_up_sync(0xffffffffu, vi[7], 1);            \
    MZI(cf[0], vr[1], vi[1], vr[2], vi[2]);                            \
    MZI(cf[1], vr[3], vi[3], vr[4], vi[4]);                            \
    MZI(cf[2], vr[5], vi[5], vr[6], vi[6]);                            \
    {   /* upper boundary: this lane's row 7 is v0 -> n0 */            \
        const float c_ = cf[3].x, sr_ = cf[3].y, si_ = cf[3].z;        \
        const float nx = c_*vr[7] - sr_*rx - si_*ry;                   \
        const float ny = c_*vi[7] - sr_*ry + si_*rx;                   \
        vr[7] = nx; vi[7] = ny;                                        \
    }                                                                  \
    {   /* lower boundary: this lane's row 0 is v1 -> n1 */            \
        const float bc = bcf.x, bs = bcf.y, bt = bcf.z;                \
        const float nx = bs*lx - bt*ly + bc*vr[0];                     \
        const float ny = bs*ly + bt*lx + bc*vi[0];                     \
        vr[0] = nx; vi[0] = ny;                                        \
    }                                                                  \
} while (0)

__global__ __launch_bounds__(128, 1) void build_u_kernel(const float* __restrict__ phi_ext) {
    const int lane = threadIdx.x & 31;
    const int j = blockIdx.x * 4 + (threadIdx.x >> 5);   // column, one per warp

    float vr[8], vi[8];
    #pragma unroll
    for (int k = 0; k < 8; ++k) {
        vr[k] = (8 * lane + k == j) ? 1.f : 0.f;
        vi[k] = 0.f;
    }

    float4 e0[4], o0[4], e1[4], o1[4], e2[4], o2[4];
    float4 b0, b1, b2;
    LOADP(e0, 0); LOADP(o0, 1); LOADB(b0, 1);
    LOADP(e1, 2); LOADP(o1, 3); LOADB(b1, 3);
    LOADP(e2, 4); LOADP(o2, 5); LOADB(b2, 5);

    int t = 6;
    #pragma unroll 1
    for (int it = 0; it < 85; ++it) {     // 85*6 = 510 steps (0..509; 509 inert)
        STEP_EVEN(e0); STEP_ODD(o0, b0);
        LOADP(e0, t); LOADP(o0, t + 1); LOADB(b0, t + 1);
        STEP_EVEN(e1); STEP_ODD(o1, b1);
        LOADP(e1, t + 2); LOADP(o1, t + 3); LOADB(b1, t + 3);
        STEP_EVEN(e2); STEP_ODD(o2, b2);
        LOADP(e2, t + 4); LOADP(o2, t + 5); LOADB(b2, t + 5);
        t += 6;
    }

    // phase screen, real part, store column j (transposed W)
    #pragma unroll
    for (int k = 0; k < 8; ++k) {
        const int r = 8 * lane + k;
        float sp, cp;
        sincosf(__ldg(&phi_ext[r]), &sp, &cp);
        g_Wt[j * NN + r] = cp * vr[k] - sp * vi[k];
    }
}

// ---------------------------------------------------------------------------
// Kernel C: out[b,i] = sum_j x[b,j] * Wt[j,i]
// BM=BN=64, BK=16, 256 threads, 4x4 per thread, float4 smem paths (pad +4).
// ---------------------------------------------------------------------------
#define BM 64
#define BN 64
#define BK 16

__global__ __launch_bounds__(256, 4) void gemm_kernel(const float* __restrict__ A,
                                                      float* __restrict__ C) {
    __shared__ float As[BK][BM + 4];
    __shared__ float Ws[BK][BN + 4];

    const int tid = threadIdx.x;
    const int tx = tid & 15;
    const int ty = tid >> 4;
    const int bm0 = blockIdx.x * BM;
    const int bn0 = blockIdx.y * BN;

    const int lr = tid >> 2;
    const int lc = (tid & 3) * 4;
    const int wr = tid >> 4;
    const int wc = (tid & 15) * 4;

    float acc[4][4] = {};

    for (int k0 = 0; k0 < NN; k0 += BK) {
        const float4 a4 = *reinterpret_cast<const float4*>(A + (bm0 + lr) * NN + k0 + lc);
        As[lc + 0][lr] = a4.x; As[lc + 1][lr] = a4.y;
        As[lc + 2][lr] = a4.z; As[lc + 3][lr] = a4.w;
        const float4 w4 = *reinterpret_cast<const float4*>(g_Wt + (k0 + wr) * NN + bn0 + wc);
        *reinterpret_cast<float4*>(&Ws[wr][wc]) = w4;
        __syncthreads();

        #pragma unroll
        for (int k = 0; k < BK; ++k) {
            const float4 am = *reinterpret_cast<const float4*>(&As[k][ty * 4]);
            const float4 bn = *reinterpret_cast<const float4*>(&Ws[k][tx * 4]);
            const float a[4] = {am.x, am.y, am.z, am.w};
            const float b[4] = {bn.x, bn.y, bn.z, bn.w};
            #pragma unroll
            for (int i = 0; i < 4; ++i)
                #pragma unroll
                for (int jj = 0; jj < 4; ++jj)
                    acc[i][jj] = fmaf(a[i], b[jj], acc[i][jj]);
        }
        __syncthreads();
    }

    #pragma unroll
    for (int i = 0; i < 4; ++i) {
        float4 r = make_float4(acc[i][0], acc[i][1], acc[i][2], acc[i][3]);
        *reinterpret_cast<float4*>(C + (bm0 + ty * 4 + i) * NN + bn0 + tx * 4) = r;
    }
}

// ---------------------------------------------------------------------------
// Launch: inputs (metadata order): x, theta, phi_internal, phi_external
// ---------------------------------------------------------------------------
extern "C" void kernel_launch(void* const* d_in, const int* in_sizes, int n_in,
                              void* d_out, int out_size) {
    const float* x       = (const float*)d_in[0];
    const float* theta   = (const float*)d_in[1];
    const float* phi_int = (const float*)d_in[2];
    const float* phi_ext = (const float*)d_in[3];
    float* out = (float*)d_out;

    coef2_kernel<<<TROWS, 128>>>(theta, phi_int);
    build_u_kernel<<<NN / 4, 128>>>(phi_ext);
    gemm_kernel<<<dim3(BATCH / BM, NN / BN), 256>>>(x, out);
}